// round 3
// baseline (speedup 1.0000x reference)
#include <cuda_runtime.h>
#include <cuda_bf16.h>
#include <cstdint>

// ---------------------------------------------------------------------------
// WaveFDTD2D, temporal blocking K=4, 128 persistent CTAs x 512 threads.
// Hierarchical grid barrier: 8 leaf counters (16 CTAs each) -> root (8) ->
// epoch flag; spin on epoch via plain acquire loads (no atomic contention).
// All counters are monotonic -> safe across graph replays.
// ---------------------------------------------------------------------------

#define NX      512
#define NZ      512
#define NSTEPS  512
#define NREC    128
#define KST     4
#define NBLK    (NSTEPS / KST)     // 128
#define NCTA    128
#define NTHR    512
#define RROWS   4
#define EXT     12                 // RROWS + 2*KST
#define SROW    520
#define BUF     (EXT * SROW)
#define SMEM_FLOATS (4 * BUF)      // P0,P1,P2,Coeff
#define SMEM_BYTES  (SMEM_FLOATS * 4)

#define NLEAF   8
#define LEAF_SZ 16                 // CTAs per leaf
#define PAD     32                 // 256B separation between counters

__device__ __align__(16) float g_P[2][NX * NZ];
__device__ __align__(16) float g_Q[2][NX * NZ];
__device__ unsigned long long g_leaf[NLEAF * PAD];
__device__ unsigned long long g_root[PAD];
__device__ unsigned long long g_epoch;

static __device__ __forceinline__ unsigned long long
atom_add_release(unsigned long long* p) {
    unsigned long long r;
    asm volatile("atom.add.release.gpu.u64 %0, [%1], 1;"
                 : "=l"(r) : "l"(p) : "memory");
    return r;
}
static __device__ __forceinline__ unsigned long long
atom_add_acqrel(unsigned long long* p) {
    unsigned long long r;
    asm volatile("atom.add.acq_rel.gpu.u64 %0, [%1], 1;"
                 : "=l"(r) : "l"(p) : "memory");
    return r;
}

static __device__ __forceinline__ void grid_barrier(int leaf) {
    __syncthreads();
    if (threadIdx.x == 0) {
        __threadfence();
        unsigned long long tok = atom_add_release(&g_leaf[leaf * PAD]);
        if ((tok & (unsigned long long)(LEAF_SZ - 1)) == LEAF_SZ - 1) {
            unsigned long long rt = atom_add_acqrel(&g_root[0]);
            if ((rt & (unsigned long long)(NLEAF - 1)) == NLEAF - 1)
                atom_add_release(&g_epoch);
        }
        const unsigned long long target = tok / LEAF_SZ + 1ULL;
        unsigned long long v;
        do {
            asm volatile("ld.acquire.gpu.u64 %0, [%1];"
                         : "=l"(v) : "l"(&g_epoch) : "memory");
        } while (v < target);
    }
    __syncthreads();
}

// One stencil substep over SMEM rows [lo,hi] (clamped to in-grid rows).
static __device__ __forceinline__ void substep(
    const float* __restrict__ Sl, const float* __restrict__ So,
    float* __restrict__ Sd, const float* __restrict__ Cc,
    int lo, int hi, int g0, int tx, int ty,
    int sx, int sz, const float* __restrict__ source, int t)
{
    const float INV  = 0.01f;
    const float DT2f = 1.0e-6f;
    int ilo = lo; { int c = 4 - g0;   if (c > ilo) ilo = c; }
    int ihi = hi; { int c = 515 - g0; if (c < ihi) ihi = c; }
    const int colbase = 4 + tx * 4;
    for (int i = ilo + ty; i <= ihi; i += 4) {
        const int base = i * SROW + colbase;
        const float4 m  = *reinterpret_cast<const float4*>(Sl + base);
        const float4 u  = *reinterpret_cast<const float4*>(Sl + base - SROW);
        const float4 d  = *reinterpret_cast<const float4*>(Sl + base + SROW);
        const float  lf = Sl[base - 1];
        const float  rg = Sl[base + 4];
        const float4 o  = *reinterpret_cast<const float4*>(So + base);
        const float4 cf = *reinterpret_cast<const float4*>(Cc + base);
        float4 nw; float lap;
        lap  = ((((u.x + d.x) + lf)  + m.y) - 4.0f * m.x) * INV;
        nw.x = (2.0f * m.x - o.x) + cf.x * lap;
        lap  = ((((u.y + d.y) + m.x) + m.z) - 4.0f * m.y) * INV;
        nw.y = (2.0f * m.y - o.y) + cf.y * lap;
        lap  = ((((u.z + d.z) + m.y) + m.w) - 4.0f * m.z) * INV;
        nw.z = (2.0f * m.z - o.z) + cf.z * lap;
        lap  = ((((u.w + d.w) + m.z) + rg)  - 4.0f * m.w) * INV;
        nw.w = (2.0f * m.w - o.w) + cf.w * lap;
        const int g = g0 - 4 + i;
        if (g == sx && (sz >> 2) == tx) {
            reinterpret_cast<float*>(&nw)[sz & 3] += __ldg(source + t) * DT2f;
        }
        *reinterpret_cast<float4*>(Sd + base) = nw;
    }
}

__global__ void __launch_bounds__(NTHR, 1)
wave_fdtd_tb_kernel(const float* __restrict__ vel,
                    const float* __restrict__ source,
                    const int*   __restrict__ p_srcx,
                    const int*   __restrict__ p_srcz,
                    const int*   __restrict__ rec_x,
                    const int*   __restrict__ rec_z,
                    float*       __restrict__ out)
{
    extern __shared__ float sm[];
    float* P0 = sm;
    float* P1 = sm + BUF;
    float* P2 = sm + 2 * BUF;
    float* Cc = sm + 3 * BUF;

    const int tid  = threadIdx.x;
    const int bid  = blockIdx.x;
    const int leaf = bid & (NLEAF - 1);
    const int g0   = bid * RROWS;
    const int tx   = tid & 127;
    const int ty   = tid >> 7;       // 0..3

    const int sx = p_srcx[0];
    const int sz = p_srcz[0];

    int my_rx = -1, my_rz = 0;
    if (tid < NREC) { my_rx = __ldg(rec_x + tid); my_rz = __ldg(rec_z + tid); }

    // ---- zero all SMEM (halo rows/cols must be and stay zero) ----
    for (int i = tid; i < SMEM_FLOATS; i += NTHR) sm[i] = 0.0f;
    __syncthreads();

    // ---- coefficient v^2*dt^2 cached in SMEM (rows 1..10) ----
    const float DT2f = 1.0e-6f;
    for (int idx = tid; idx < 10 * 128; idx += NTHR) {
        const int r = 1 + (idx >> 7), c = idx & 127;
        const int g = g0 - 4 + r;
        if ((unsigned)g < (unsigned)NX) {
            const float4 v = __ldg(reinterpret_cast<const float4*>(
                                   vel + (size_t)g * NZ + c * 4));
            *reinterpret_cast<float4*>(Cc + r * SROW + 4 + c * 4) =
                make_float4(v.x * v.x * DT2f, v.y * v.y * DT2f,
                            v.z * v.z * DT2f, v.w * v.w * DT2f);
        }
    }

    // ---- zero global state (pair 0 read by block 0) ----
    {
        const float4 z = make_float4(0.f, 0.f, 0.f, 0.f);
        float4* p = reinterpret_cast<float4*>(g_P[0]);
        float4* q = reinterpret_cast<float4*>(g_Q[0]);
        for (int i = bid * NTHR + tid; i < NX * NZ / 4; i += NCTA * NTHR) {
            __stcg(p + i, z);
            __stcg(q + i, z);
        }
    }
    grid_barrier(leaf);

    for (int b = 0; b < NBLK; ++b) {
        const int pb = b & 1;
        const float* gp = g_P[pb];
        const float* gq = g_Q[pb];

        // ---- load p_n (rows 0..11) and p_{n-1} (rows 1..10) ----
        for (int idx = tid; idx < EXT * 128; idx += NTHR) {
            const int r = idx >> 7, c = idx & 127;
            const int g = g0 - 4 + r;
            if ((unsigned)g < (unsigned)NX)
                *reinterpret_cast<float4*>(P1 + r * SROW + 4 + c * 4) =
                    __ldcg(reinterpret_cast<const float4*>(gp + (size_t)g * NZ + c * 4));
        }
        for (int idx = tid; idx < 10 * 128; idx += NTHR) {
            const int r = 1 + (idx >> 7), c = idx & 127;
            const int g = g0 - 4 + r;
            if ((unsigned)g < (unsigned)NX)
                *reinterpret_cast<float4*>(P0 + r * SROW + 4 + c * 4) =
                    __ldcg(reinterpret_cast<const float4*>(gq + (size_t)g * NZ + c * 4));
        }
        __syncthreads();

        const int t0 = b * KST;

        substep(P1, P0, P2, Cc, 1, 10, g0, tx, ty, sx, sz, source, t0);
        __syncthreads();
        if (my_rx >= 0 && (my_rx >> 2) == bid)
            out[(size_t)tid * NSTEPS + t0] =
                P2[(4 + (my_rx & 3)) * SROW + 4 + my_rz];

        substep(P2, P1, P0, Cc, 2, 9, g0, tx, ty, sx, sz, source, t0 + 1);
        __syncthreads();
        if (my_rx >= 0 && (my_rx >> 2) == bid)
            out[(size_t)tid * NSTEPS + t0 + 1] =
                P0[(4 + (my_rx & 3)) * SROW + 4 + my_rz];

        substep(P0, P2, P1, Cc, 3, 8, g0, tx, ty, sx, sz, source, t0 + 2);
        __syncthreads();
        if (my_rx >= 0 && (my_rx >> 2) == bid)
            out[(size_t)tid * NSTEPS + t0 + 2] =
                P1[(4 + (my_rx & 3)) * SROW + 4 + my_rz];

        substep(P1, P0, P2, Cc, 4, 7, g0, tx, ty, sx, sz, source, t0 + 3);
        __syncthreads();
        if (my_rx >= 0 && (my_rx >> 2) == bid)
            out[(size_t)tid * NSTEPS + t0 + 3] =
                P2[(4 + (my_rx & 3)) * SROW + 4 + my_rz];

        // ---- store p_{n+4} (P2) and p_{n+3} (P1), own rows, other pair ----
        float* gpo = g_P[pb ^ 1];
        float* gqo = g_Q[pb ^ 1];
        for (int idx = tid; idx < RROWS * 128; idx += NTHR) {
            const int r = 4 + (idx >> 7), c = idx & 127;
            const int g = g0 - 4 + r;
            __stcg(reinterpret_cast<float4*>(gpo + (size_t)g * NZ + c * 4),
                   *reinterpret_cast<const float4*>(P2 + r * SROW + 4 + c * 4));
            __stcg(reinterpret_cast<float4*>(gqo + (size_t)g * NZ + c * 4),
                   *reinterpret_cast<const float4*>(P1 + r * SROW + 4 + c * 4));
        }
        grid_barrier(leaf);
    }
}

extern "C" void kernel_launch(void* const* d_in, const int* in_sizes, int n_in,
                              void* d_out, int out_size)
{
    const float* vel    = (const float*)d_in[0];
    const float* source = (const float*)d_in[1];
    const int*   srcx   = (const int*)d_in[2];
    const int*   srcz   = (const int*)d_in[3];
    const int*   rec_x  = (const int*)d_in[4];
    const int*   rec_z  = (const int*)d_in[5];
    float* out = (float*)d_out;

    cudaFuncSetAttribute(wave_fdtd_tb_kernel,
                         cudaFuncAttributeMaxDynamicSharedMemorySize, SMEM_BYTES);
    wave_fdtd_tb_kernel<<<NCTA, NTHR, SMEM_BYTES>>>(
        vel, source, srcx, srcz, rec_x, rec_z, out);
}

// round 4
// speedup vs baseline: 1.2365x; 1.2365x over previous
#include <cuda_runtime.h>
#include <cuda_bf16.h>
#include <cstdint>

// ---------------------------------------------------------------------------
// WaveFDTD2D, temporal blocking K=4, 128 persistent CTAs x 256 threads.
// NEIGHBOR-ONLY synchronization: per-CTA monotonic done counters; CTA b waits
// only for CTAs b-1/b+1 (halo depth 4 rows = exactly one neighbor). No global
// barrier -> no 128-way atomic serialization, skew pipelines as a wavefront.
// SMEM buffer rotation carries own rows across blocks (only halos reload).
// ---------------------------------------------------------------------------

#define NX      512
#define NZ      512
#define NSTEPS  512
#define NREC    128
#define KST     4
#define NBLK    (NSTEPS / KST)     // 128
#define NCTA    128
#define NTHR    256
#define RROWS   4
#define EXT     12                 // RROWS + 2*KST
#define SROW    520
#define BUF     (EXT * SROW)
#define SMEM_FLOATS (4 * BUF)      // S0,S1,S2,Coeff
#define SMEM_BYTES  (SMEM_FLOATS * 4)
#define PAD     32                 // 256B between counters

__device__ __align__(16) float g_P[2][NX * NZ];
__device__ __align__(16) float g_Q[2][NX * NZ];
__device__ unsigned long long g_done[NCTA * PAD];   // monotonic, never reset

static __device__ __forceinline__ void signal_done(int bid) {
    // caller guarantees __syncthreads() before this (all CTA stores issued)
    __threadfence();
    asm volatile("red.add.release.gpu.u64 [%0], 1;"
                 :: "l"(&g_done[bid * PAD]) : "memory");
}
static __device__ __forceinline__ void wait_ge(int nbid, unsigned long long tgt) {
    unsigned long long v;
    do {
        asm volatile("ld.acquire.gpu.u64 %0, [%1];"
                     : "=l"(v) : "l"(&g_done[nbid * PAD]) : "memory");
    } while (v < tgt);
}

// One stencil substep over SMEM rows [lo,hi] (clamped to in-grid rows).
static __device__ __forceinline__ void substep(
    const float* __restrict__ Sl, const float* __restrict__ So,
    float* __restrict__ Sd, const float* __restrict__ Cc,
    int lo, int hi, int g0, int tx, int ty,
    int sx, int sz, const float* __restrict__ source, int t)
{
    const float INV  = 0.01f;    // 1/(dx*dz)
    const float DT2f = 1.0e-6f;  // dt^2
    int ilo = lo; { int c = 4 - g0;   if (c > ilo) ilo = c; }
    int ihi = hi; { int c = 515 - g0; if (c < ihi) ihi = c; }
    const int colbase = 4 + tx * 4;
    for (int i = ilo + ty; i <= ihi; i += 2) {
        const int base = i * SROW + colbase;
        const float4 m  = *reinterpret_cast<const float4*>(Sl + base);
        const float4 u  = *reinterpret_cast<const float4*>(Sl + base - SROW);
        const float4 d  = *reinterpret_cast<const float4*>(Sl + base + SROW);
        const float  lf = Sl[base - 1];
        const float  rg = Sl[base + 4];
        const float4 o  = *reinterpret_cast<const float4*>(So + base);
        const float4 cf = *reinterpret_cast<const float4*>(Cc + base);
        float4 nw; float lap;
        lap  = ((((u.x + d.x) + lf)  + m.y) - 4.0f * m.x) * INV;
        nw.x = (2.0f * m.x - o.x) + cf.x * lap;
        lap  = ((((u.y + d.y) + m.x) + m.z) - 4.0f * m.y) * INV;
        nw.y = (2.0f * m.y - o.y) + cf.y * lap;
        lap  = ((((u.z + d.z) + m.y) + m.w) - 4.0f * m.z) * INV;
        nw.z = (2.0f * m.z - o.z) + cf.z * lap;
        lap  = ((((u.w + d.w) + m.z) + rg)  - 4.0f * m.w) * INV;
        nw.w = (2.0f * m.w - o.w) + cf.w * lap;
        const int g = g0 - 4 + i;
        if (g == sx && (sz >> 2) == tx) {
            reinterpret_cast<float*>(&nw)[sz & 3] += __ldg(source + t) * DT2f;
        }
        *reinterpret_cast<float4*>(Sd + base) = nw;
    }
}

__global__ void __launch_bounds__(NTHR, 1)
wave_fdtd_nb_kernel(const float* __restrict__ vel,
                    const float* __restrict__ source,
                    const int*   __restrict__ p_srcx,
                    const int*   __restrict__ p_srcz,
                    const int*   __restrict__ rec_x,
                    const int*   __restrict__ rec_z,
                    float*       __restrict__ out)
{
    extern __shared__ float sm[];
    __shared__ unsigned long long sm_base;
    float* Cc = sm + 3 * BUF;

    const int tid = threadIdx.x;
    const int bid = blockIdx.x;
    const int g0  = bid * RROWS;
    const int tx  = tid & 127;
    const int ty  = tid >> 7;    // 0..1

    const int sx = p_srcx[0];
    const int sz = p_srcz[0];

    int my_rx = -1, my_rz = 0;
    if (tid < NREC) { my_rx = __ldg(rec_x + tid); my_rz = __ldg(rec_z + tid); }
    const bool my_rec = (my_rx >= 0) && ((my_rx >> 2) == bid);
    const int  rec_off = my_rec ? ((4 + (my_rx & 3)) * SROW + 4 + my_rz) : 0;

    // ---- zero all SMEM; read own counter base ----
    for (int i = tid; i < SMEM_FLOATS; i += NTHR) sm[i] = 0.0f;
    if (tid == 0) sm_base = g_done[bid * PAD];   // only self ever writes it
    __syncthreads();
    const unsigned long long base = sm_base;

    // ---- coefficients v^2*dt^2 into SMEM rows 1..10 ----
    const float DT2f = 1.0e-6f;
    for (int idx = tid; idx < 10 * 128; idx += NTHR) {
        const int r = 1 + (idx >> 7), c = idx & 127;
        const int g = g0 - 4 + r;
        if ((unsigned)g < (unsigned)NX) {
            const float4 v = __ldg(reinterpret_cast<const float4*>(
                                   vel + (size_t)g * NZ + c * 4));
            *reinterpret_cast<float4*>(Cc + r * SROW + 4 + c * 4) =
                make_float4(v.x * v.x * DT2f, v.y * v.y * DT2f,
                            v.z * v.z * DT2f, v.w * v.w * DT2f);
        }
    }

    // ---- zero OWN rows of global pair 0 (stale from prior replay) ----
    {
        const float4 z = make_float4(0.f, 0.f, 0.f, 0.f);
        for (int idx = tid; idx < RROWS * 128; idx += NTHR) {
            const int r = idx >> 7, c = idx & 127;
            const size_t off = (size_t)(g0 + r) * NZ + c * 4;
            __stcg(reinterpret_cast<float4*>(g_P[0] + off), z);
            __stcg(reinterpret_cast<float4*>(g_Q[0] + off), z);
        }
    }
    __syncthreads();
    if (tid == 0) signal_done(bid);   // counter -> base+1

    // SMEM buffer roles: A = p_n (Laplacian src), B = p_{n-1}, C = scratch
    float* A = sm;
    float* B = sm + BUF;
    float* C = sm + 2 * BUF;

    for (int b = 0; b < NBLK; ++b) {
        // ---- wait for neighbors to finish block b-1 (and zeroing) ----
        if (tid == 0) {
            const unsigned long long tgt = base + 1 + (unsigned long long)b;
            if (bid > 0)        wait_ge(bid - 1, tgt);
            if (bid < NCTA - 1) wait_ge(bid + 1, tgt);
        }
        __syncthreads();

        const int pb = b & 1;
        const float* gp = g_P[pb];
        const float* gq = g_Q[pb];

        // ---- load halos only: A rows {0..3, 8..11}, B rows {1,2,9,10} ----
        for (int idx = tid; idx < 8 * 128; idx += NTHR) {
            const int r0 = idx >> 7, c = idx & 127;
            const int r = (r0 < 4) ? r0 : r0 + 4;
            const int g = g0 - 4 + r;
            if ((unsigned)g < (unsigned)NX)
                *reinterpret_cast<float4*>(A + r * SROW + 4 + c * 4) =
                    __ldcg(reinterpret_cast<const float4*>(gp + (size_t)g * NZ + c * 4));
        }
        for (int idx = tid; idx < 4 * 128; idx += NTHR) {
            const int r0 = idx >> 7, c = idx & 127;
            const int r = (r0 < 2) ? r0 + 1 : r0 + 7;   // 1,2,9,10
            const int g = g0 - 4 + r;
            if ((unsigned)g < (unsigned)NX)
                *reinterpret_cast<float4*>(B + r * SROW + 4 + c * 4) =
                    __ldcg(reinterpret_cast<const float4*>(gq + (size_t)g * NZ + c * 4));
        }
        __syncthreads();

        const int t0 = b * KST;

        // s1: p_{n+1} = f(A, B) -> C, rows [1,10]
        substep(A, B, C, Cc, 1, 10, g0, tx, ty, sx, sz, source, t0);
        __syncthreads();
        if (my_rec) out[(size_t)tid * NSTEPS + t0] = C[rec_off];

        // s2: p_{n+2} = f(C, A) -> B, rows [2,9]
        substep(C, A, B, Cc, 2, 9, g0, tx, ty, sx, sz, source, t0 + 1);
        __syncthreads();
        if (my_rec) out[(size_t)tid * NSTEPS + t0 + 1] = B[rec_off];

        // s3: p_{n+3} = f(B, C) -> A, rows [3,8]
        substep(B, C, A, Cc, 3, 8, g0, tx, ty, sx, sz, source, t0 + 2);
        __syncthreads();
        if (my_rec) out[(size_t)tid * NSTEPS + t0 + 2] = A[rec_off];

        // s4: p_{n+4} = f(A, B) -> C, rows [4,7] (own rows)
        substep(A, B, C, Cc, 4, 7, g0, tx, ty, sx, sz, source, t0 + 3);
        __syncthreads();
        if (my_rec) out[(size_t)tid * NSTEPS + t0 + 3] = C[rec_off];

        // ---- store own rows for neighbors: C -> P[pb^1], A -> Q[pb^1] ----
        float* gpo = g_P[pb ^ 1];
        float* gqo = g_Q[pb ^ 1];
        for (int idx = tid; idx < RROWS * 128; idx += NTHR) {
            const int r = 4 + (idx >> 7), c = idx & 127;
            const size_t off = (size_t)(g0 - 4 + r) * NZ + c * 4;
            __stcg(reinterpret_cast<float4*>(gpo + off),
                   *reinterpret_cast<const float4*>(C + r * SROW + 4 + c * 4));
            __stcg(reinterpret_cast<float4*>(gqo + off),
                   *reinterpret_cast<const float4*>(A + r * SROW + 4 + c * 4));
        }
        __syncthreads();
        if (tid == 0) signal_done(bid);   // counter -> base+2+b

        // ---- rotate: A' = C (newest, own rows), B' = A (2nd newest), C' = B
        float* tmp = A; A = C; C = B; B = tmp;
    }
}

extern "C" void kernel_launch(void* const* d_in, const int* in_sizes, int n_in,
                              void* d_out, int out_size)
{
    const float* vel    = (const float*)d_in[0];
    const float* source = (const float*)d_in[1];
    const int*   srcx   = (const int*)d_in[2];
    const int*   srcz   = (const int*)d_in[3];
    const int*   rec_x  = (const int*)d_in[4];
    const int*   rec_z  = (const int*)d_in[5];
    float* out = (float*)d_out;

    cudaFuncSetAttribute(wave_fdtd_nb_kernel,
                         cudaFuncAttributeMaxDynamicSharedMemorySize, SMEM_BYTES);
    wave_fdtd_nb_kernel<<<NCTA, NTHR, SMEM_BYTES>>>(
        vel, source, srcx, srcz, rec_x, rec_z, out);
}

// round 5
// speedup vs baseline: 1.4510x; 1.1735x over previous
#include <cuda_runtime.h>
#include <cuda_bf16.h>
#include <cstdint>

// ---------------------------------------------------------------------------
// WaveFDTD2D, temporal blocking K=4, 128 persistent CTAs x 512 threads.
// Neighbor-only sync (per-CTA monotonic counters, concurrent polls).
// SMEM rotation carries own rows; only halos reload from L2.
// Global stores of own rows folded into substeps s3/s4.
// ---------------------------------------------------------------------------

#define NX      512
#define NZ      512
#define NSTEPS  512
#define NREC    128
#define KST     4
#define NBLK    (NSTEPS / KST)     // 128
#define NCTA    128
#define NTHR    512
#define RROWS   4
#define EXT     12                 // RROWS + 2*KST
#define SROW    520
#define BUF     (EXT * SROW)
#define SMEM_FLOATS (4 * BUF)      // A,B,C,Coeff
#define SMEM_BYTES  (SMEM_FLOATS * 4)
#define PAD     32                 // 256B between counters

__device__ __align__(16) float g_P[2][NX * NZ];
__device__ __align__(16) float g_Q[2][NX * NZ];
__device__ unsigned long long g_done[NCTA * PAD];   // monotonic, never reset

static __device__ __forceinline__ void signal_done(int bid) {
    __threadfence();
    asm volatile("red.add.release.gpu.u64 [%0], 1;"
                 :: "l"(&g_done[bid * PAD]) : "memory");
}

// Wait until BOTH neighbor counters reach tgt (polls issued concurrently).
static __device__ __forceinline__ void wait_neighbors(int bid, unsigned long long tgt) {
    const unsigned long long* lo =
        (bid > 0) ? &g_done[(bid - 1) * PAD] : nullptr;
    const unsigned long long* hi =
        (bid < NCTA - 1) ? &g_done[(bid + 1) * PAD] : nullptr;
    bool need_lo = (lo != nullptr), need_hi = (hi != nullptr);
    while (need_lo || need_hi) {
        unsigned long long a = tgt, b = tgt;
        if (need_lo)
            asm volatile("ld.acquire.gpu.u64 %0, [%1];" : "=l"(a) : "l"(lo) : "memory");
        if (need_hi)
            asm volatile("ld.acquire.gpu.u64 %0, [%1];" : "=l"(b) : "l"(hi) : "memory");
        if (a >= tgt) need_lo = false;
        if (b >= tgt) need_hi = false;
    }
}

// One stencil substep over SMEM rows [lo,hi] (clamped to in-grid rows).
// If gdst != nullptr, rows 4..7 (own rows) are also stored to gdst.
static __device__ __forceinline__ void substep(
    const float* __restrict__ Sl, const float* __restrict__ So,
    float* __restrict__ Sd, const float* __restrict__ Cc,
    int lo, int hi, int g0, int tx, int ty,
    int sx, int sz, const float* __restrict__ source, int t,
    float* __restrict__ gdst)
{
    const float INV  = 0.01f;    // 1/(dx*dz)
    const float DT2f = 1.0e-6f;  // dt^2
    int ilo = lo; { int c = 4 - g0;   if (c > ilo) ilo = c; }
    int ihi = hi; { int c = 515 - g0; if (c < ihi) ihi = c; }
    const int colbase = 4 + tx * 4;
    for (int i = ilo + ty; i <= ihi; i += 4) {
        const int base = i * SROW + colbase;
        const float4 m  = *reinterpret_cast<const float4*>(Sl + base);
        const float4 u  = *reinterpret_cast<const float4*>(Sl + base - SROW);
        const float4 d  = *reinterpret_cast<const float4*>(Sl + base + SROW);
        const float  lf = Sl[base - 1];
        const float  rg = Sl[base + 4];
        const float4 o  = *reinterpret_cast<const float4*>(So + base);
        const float4 cf = *reinterpret_cast<const float4*>(Cc + base);
        float4 nw; float lap;
        lap  = ((((u.x + d.x) + lf)  + m.y) - 4.0f * m.x) * INV;
        nw.x = (2.0f * m.x - o.x) + cf.x * lap;
        lap  = ((((u.y + d.y) + m.x) + m.z) - 4.0f * m.y) * INV;
        nw.y = (2.0f * m.y - o.y) + cf.y * lap;
        lap  = ((((u.z + d.z) + m.y) + m.w) - 4.0f * m.z) * INV;
        nw.z = (2.0f * m.z - o.z) + cf.z * lap;
        lap  = ((((u.w + d.w) + m.z) + rg)  - 4.0f * m.w) * INV;
        nw.w = (2.0f * m.w - o.w) + cf.w * lap;
        const int g = g0 - 4 + i;
        if (g == sx && (sz >> 2) == tx) {
            reinterpret_cast<float*>(&nw)[sz & 3] += __ldg(source + t) * DT2f;
        }
        *reinterpret_cast<float4*>(Sd + base) = nw;
        if (gdst != nullptr && i >= 4 && i <= 7) {
            __stcg(reinterpret_cast<float4*>(gdst + (size_t)g * NZ + tx * 4), nw);
        }
    }
}

__global__ void __launch_bounds__(NTHR, 1)
wave_fdtd_nb_kernel(const float* __restrict__ vel,
                    const float* __restrict__ source,
                    const int*   __restrict__ p_srcx,
                    const int*   __restrict__ p_srcz,
                    const int*   __restrict__ rec_x,
                    const int*   __restrict__ rec_z,
                    float*       __restrict__ out)
{
    extern __shared__ float sm[];
    __shared__ unsigned long long sm_base;
    float* Cc = sm + 3 * BUF;

    const int tid = threadIdx.x;
    const int bid = blockIdx.x;
    const int g0  = bid * RROWS;
    const int tx  = tid & 127;
    const int ty  = tid >> 7;    // 0..3

    const int sx = p_srcx[0];
    const int sz = p_srcz[0];

    int my_rx = -1, my_rz = 0;
    if (tid < NREC) { my_rx = __ldg(rec_x + tid); my_rz = __ldg(rec_z + tid); }
    const bool my_rec = (my_rx >= 0) && ((my_rx >> 2) == bid);
    const int  rec_off = my_rec ? ((4 + (my_rx & 3)) * SROW + 4 + my_rz) : 0;

    // ---- zero all SMEM; read own counter base ----
    for (int i = tid; i < SMEM_FLOATS; i += NTHR) sm[i] = 0.0f;
    if (tid == 0) sm_base = g_done[bid * PAD];   // only self ever increments it
    __syncthreads();
    const unsigned long long base = sm_base;

    // ---- coefficients v^2*dt^2 into SMEM rows 1..10 ----
    const float DT2f = 1.0e-6f;
    for (int idx = tid; idx < 10 * 128; idx += NTHR) {
        const int r = 1 + (idx >> 7), c = idx & 127;
        const int g = g0 - 4 + r;
        if ((unsigned)g < (unsigned)NX) {
            const float4 v = __ldg(reinterpret_cast<const float4*>(
                                   vel + (size_t)g * NZ + c * 4));
            *reinterpret_cast<float4*>(Cc + r * SROW + 4 + c * 4) =
                make_float4(v.x * v.x * DT2f, v.y * v.y * DT2f,
                            v.z * v.z * DT2f, v.w * v.w * DT2f);
        }
    }

    // ---- zero OWN rows of global pair 0 (stale from prior replay) ----
    {
        const float4 z = make_float4(0.f, 0.f, 0.f, 0.f);
        for (int idx = tid; idx < RROWS * 128; idx += NTHR) {
            const int r = idx >> 7, c = idx & 127;
            const size_t off = (size_t)(g0 + r) * NZ + c * 4;
            __stcg(reinterpret_cast<float4*>(g_P[0] + off), z);
            __stcg(reinterpret_cast<float4*>(g_Q[0] + off), z);
        }
    }
    __syncthreads();
    if (tid == 0) signal_done(bid);   // counter -> base+1

    // SMEM roles: A = p_n (Laplacian src), B = p_{n-1}, C = scratch
    float* A = sm;
    float* B = sm + BUF;
    float* C = sm + 2 * BUF;

    for (int b = 0; b < NBLK; ++b) {
        if (tid == 0)
            wait_neighbors(bid, base + 1 + (unsigned long long)b);
        __syncthreads();

        const int pb = b & 1;
        const float* gp = g_P[pb];
        const float* gq = g_Q[pb];

        // ---- load halos only: A rows {0..3, 8..11}, B rows {1,2,9,10} ----
        for (int idx = tid; idx < 8 * 128; idx += NTHR) {
            const int r0 = idx >> 7, c = idx & 127;
            const int r = (r0 < 4) ? r0 : r0 + 4;
            const int g = g0 - 4 + r;
            if ((unsigned)g < (unsigned)NX)
                *reinterpret_cast<float4*>(A + r * SROW + 4 + c * 4) =
                    __ldcg(reinterpret_cast<const float4*>(gp + (size_t)g * NZ + c * 4));
        }
        for (int idx = tid; idx < 4 * 128; idx += NTHR) {
            const int r0 = idx >> 7, c = idx & 127;
            const int r = (r0 < 2) ? r0 + 1 : r0 + 7;   // 1,2,9,10
            const int g = g0 - 4 + r;
            if ((unsigned)g < (unsigned)NX)
                *reinterpret_cast<float4*>(B + r * SROW + 4 + c * 4) =
                    __ldcg(reinterpret_cast<const float4*>(gq + (size_t)g * NZ + c * 4));
        }
        __syncthreads();

        const int t0 = b * KST;
        float* gpo = g_P[pb ^ 1];
        float* gqo = g_Q[pb ^ 1];

        // s1: p_{n+1} = f(A, B) -> C, rows [1,10]
        substep(A, B, C, Cc, 1, 10, g0, tx, ty, sx, sz, source, t0, nullptr);
        __syncthreads();
        if (my_rec) out[(size_t)tid * NSTEPS + t0] = C[rec_off];

        // s2: p_{n+2} = f(C, A) -> B, rows [2,9]
        substep(C, A, B, Cc, 2, 9, g0, tx, ty, sx, sz, source, t0 + 1, nullptr);
        __syncthreads();
        if (my_rec) out[(size_t)tid * NSTEPS + t0 + 1] = B[rec_off];

        // s3: p_{n+3} = f(B, C) -> A, rows [3,8]; own rows also -> Q[pb^1]
        substep(B, C, A, Cc, 3, 8, g0, tx, ty, sx, sz, source, t0 + 2, gqo);
        __syncthreads();
        if (my_rec) out[(size_t)tid * NSTEPS + t0 + 2] = A[rec_off];

        // s4: p_{n+4} = f(A, B) -> C, rows [4,7]; own rows also -> P[pb^1]
        substep(A, B, C, Cc, 4, 7, g0, tx, ty, sx, sz, source, t0 + 3, gpo);
        __syncthreads();
        if (my_rec) out[(size_t)tid * NSTEPS + t0 + 3] = C[rec_off];

        if (tid == 0) signal_done(bid);   // counter -> base+2+b

        // rotate: A' = C (newest), B' = A, C' = B
        float* tmp = A; A = C; C = B; B = tmp;
    }
}

extern "C" void kernel_launch(void* const* d_in, const int* in_sizes, int n_in,
                              void* d_out, int out_size)
{
    const float* vel    = (const float*)d_in[0];
    const float* source = (const float*)d_in[1];
    const int*   srcx   = (const int*)d_in[2];
    const int*   srcz   = (const int*)d_in[3];
    const int*   rec_x  = (const int*)d_in[4];
    const int*   rec_z  = (const int*)d_in[5];
    float* out = (float*)d_out;

    cudaFuncSetAttribute(wave_fdtd_nb_kernel,
                         cudaFuncAttributeMaxDynamicSharedMemorySize, SMEM_BYTES);
    wave_fdtd_nb_kernel<<<NCTA, NTHR, SMEM_BYTES>>>(
        vel, source, srcx, srcz, rec_x, rec_z, out);
}

// round 6
// speedup vs baseline: 1.5412x; 1.0622x over previous
#include <cuda_runtime.h>
#include <cuda_bf16.h>
#include <cstdint>

// ---------------------------------------------------------------------------
// WaveFDTD2D, temporal blocking K=4, 128 persistent CTAs x 512 threads.
// Neighbor-only sync (per-CTA monotonic counters). SMEM rotation carries own
// rows; only halos reload from L2. Substeps are compile-time unrolled
// (template bounds) so LDS issues batch across rows -> latency hidden.
// ---------------------------------------------------------------------------

#define NX      512
#define NZ      512
#define NSTEPS  512
#define NREC    128
#define KST     4
#define NBLK    (NSTEPS / KST)     // 128
#define NCTA    128
#define NTHR    512
#define RROWS   4
#define EXT     12                 // RROWS + 2*KST
#define SROW    520
#define BUF     (EXT * SROW)
#define SMEM_FLOATS (4 * BUF)      // A,B,C,Coeff
#define SMEM_BYTES  (SMEM_FLOATS * 4)
#define PAD     32                 // 256B between counters

__device__ __align__(16) float g_P[2][NX * NZ];
__device__ __align__(16) float g_Q[2][NX * NZ];
__device__ unsigned long long g_done[NCTA * PAD];   // monotonic, never reset

static __device__ __forceinline__ void signal_done(int bid) {
    // red.release orders all prior writes at gpu scope (no extra membar)
    asm volatile("red.add.release.gpu.u64 [%0], 1;"
                 :: "l"(&g_done[bid * PAD]) : "memory");
}

static __device__ __forceinline__ void wait_neighbors(int bid, unsigned long long tgt) {
    const unsigned long long* lo =
        (bid > 0) ? &g_done[(bid - 1) * PAD] : nullptr;
    const unsigned long long* hi =
        (bid < NCTA - 1) ? &g_done[(bid + 1) * PAD] : nullptr;
    bool need_lo = (lo != nullptr), need_hi = (hi != nullptr);
    while (need_lo || need_hi) {
        unsigned long long a = tgt, b = tgt;
        if (need_lo)
            asm volatile("ld.acquire.gpu.u64 %0, [%1];" : "=l"(a) : "l"(lo) : "memory");
        if (need_hi)
            asm volatile("ld.acquire.gpu.u64 %0, [%1];" : "=l"(b) : "l"(hi) : "memory");
        if (a >= tgt) need_lo = false;
        if (b >= tgt) need_hi = false;
    }
}

// One stencil substep over SMEM rows [LO,HI] (compile-time), fully unrolled.
// rlo/rhi: runtime in-grid clamp (non-trivial only for CTAs 0 and 127).
// If STORE, own rows (4..7) are also written to gdst.
template<int LO, int HI, bool STORE>
static __device__ __forceinline__ void substep(
    const float* __restrict__ Sl, const float* __restrict__ So,
    float* __restrict__ Sd, const float* __restrict__ Cc,
    int rlo, int rhi, int g0, int tx, int ty,
    int sx, int sz, const float* __restrict__ source, int t,
    float* __restrict__ gdst)
{
    const float INV  = 0.01f;    // 1/(dx*dz)
    const float DT2f = 1.0e-6f;  // dt^2
    const int colbase = 4 + tx * 4;
    #pragma unroll
    for (int k = 0; k < (HI - LO) / 4 + 1; ++k) {
        const int i = LO + ty + 4 * k;
        if (i > HI) continue;                 // ty-dependent tail
        if (i < rlo || i > rhi) continue;     // grid-edge clamp (CTA 0/127)
        const int base = i * SROW + colbase;
        const float4 m  = *reinterpret_cast<const float4*>(Sl + base);
        const float4 u  = *reinterpret_cast<const float4*>(Sl + base - SROW);
        const float4 d  = *reinterpret_cast<const float4*>(Sl + base + SROW);
        const float  lf = Sl[base - 1];
        const float  rg = Sl[base + 4];
        const float4 o  = *reinterpret_cast<const float4*>(So + base);
        const float4 cf = *reinterpret_cast<const float4*>(Cc + base);
        float4 nw; float lap;
        lap  = ((((u.x + d.x) + lf)  + m.y) - 4.0f * m.x) * INV;
        nw.x = (2.0f * m.x - o.x) + cf.x * lap;
        lap  = ((((u.y + d.y) + m.x) + m.z) - 4.0f * m.y) * INV;
        nw.y = (2.0f * m.y - o.y) + cf.y * lap;
        lap  = ((((u.z + d.z) + m.y) + m.w) - 4.0f * m.z) * INV;
        nw.z = (2.0f * m.z - o.z) + cf.z * lap;
        lap  = ((((u.w + d.w) + m.z) + rg)  - 4.0f * m.w) * INV;
        nw.w = (2.0f * m.w - o.w) + cf.w * lap;
        const int g = g0 - 4 + i;
        if (g == sx && (sz >> 2) == tx) {
            reinterpret_cast<float*>(&nw)[sz & 3] += __ldg(source + t) * DT2f;
        }
        *reinterpret_cast<float4*>(Sd + base) = nw;
        if (STORE && i >= 4 && i <= 7) {
            __stcg(reinterpret_cast<float4*>(gdst + (size_t)g * NZ + tx * 4), nw);
        }
    }
}

__global__ void __launch_bounds__(NTHR, 1)
wave_fdtd_nb_kernel(const float* __restrict__ vel,
                    const float* __restrict__ source,
                    const int*   __restrict__ p_srcx,
                    const int*   __restrict__ p_srcz,
                    const int*   __restrict__ rec_x,
                    const int*   __restrict__ rec_z,
                    float*       __restrict__ out)
{
    extern __shared__ float sm[];
    __shared__ unsigned long long sm_base;
    float* Cc = sm + 3 * BUF;

    const int tid = threadIdx.x;
    const int bid = blockIdx.x;
    const int g0  = bid * RROWS;
    const int tx  = tid & 127;
    const int ty  = tid >> 7;    // 0..3

    const int sx = p_srcx[0];
    const int sz = p_srcz[0];

    // grid-edge clamps (identity for interior CTAs)
    const int clo = 4 - g0;        // min valid SMEM row
    const int chi = 515 - g0;      // max valid SMEM row

    int my_rx = -1, my_rz = 0;
    if (tid < NREC) { my_rx = __ldg(rec_x + tid); my_rz = __ldg(rec_z + tid); }
    const bool my_rec = (my_rx >= 0) && ((my_rx >> 2) == bid);
    const int  rec_off = my_rec ? ((4 + (my_rx & 3)) * SROW + 4 + my_rz) : 0;

    // ---- zero all SMEM; read own counter base ----
    for (int i = tid; i < SMEM_FLOATS; i += NTHR) sm[i] = 0.0f;
    if (tid == 0) sm_base = g_done[bid * PAD];   // only self ever increments it
    __syncthreads();
    const unsigned long long base = sm_base;

    // ---- coefficients v^2*dt^2 into SMEM rows 1..10 ----
    const float DT2f = 1.0e-6f;
    for (int idx = tid; idx < 10 * 128; idx += NTHR) {
        const int r = 1 + (idx >> 7), c = idx & 127;
        const int g = g0 - 4 + r;
        if ((unsigned)g < (unsigned)NX) {
            const float4 v = __ldg(reinterpret_cast<const float4*>(
                                   vel + (size_t)g * NZ + c * 4));
            *reinterpret_cast<float4*>(Cc + r * SROW + 4 + c * 4) =
                make_float4(v.x * v.x * DT2f, v.y * v.y * DT2f,
                            v.z * v.z * DT2f, v.w * v.w * DT2f);
        }
    }

    // ---- zero OWN rows of global pair 0 (stale from prior replay) ----
    {
        const float4 z = make_float4(0.f, 0.f, 0.f, 0.f);
        for (int idx = tid; idx < RROWS * 128; idx += NTHR) {
            const int r = idx >> 7, c = idx & 127;
            const size_t off = (size_t)(g0 + r) * NZ + c * 4;
            __stcg(reinterpret_cast<float4*>(g_P[0] + off), z);
            __stcg(reinterpret_cast<float4*>(g_Q[0] + off), z);
        }
    }
    __syncthreads();
    if (tid == 0) signal_done(bid);   // counter -> base+1

    // SMEM roles: A = p_n (Laplacian src), B = p_{n-1}, C = scratch
    float* A = sm;
    float* B = sm + BUF;
    float* C = sm + 2 * BUF;

    for (int b = 0; b < NBLK; ++b) {
        if (tid == 0)
            wait_neighbors(bid, base + 1 + (unsigned long long)b);
        __syncthreads();

        const int pb = b & 1;
        const float* gp = g_P[pb];
        const float* gq = g_Q[pb];

        // ---- load halos only: A rows {0..3, 8..11}, B rows {1,2,9,10} ----
        #pragma unroll
        for (int k = 0; k < 2; ++k) {
            const int idx = tid + k * NTHR;
            const int r0 = idx >> 7, c = idx & 127;
            const int r = (r0 < 4) ? r0 : r0 + 4;
            const int g = g0 - 4 + r;
            if ((unsigned)g < (unsigned)NX)
                *reinterpret_cast<float4*>(A + r * SROW + 4 + c * 4) =
                    __ldcg(reinterpret_cast<const float4*>(gp + (size_t)g * NZ + c * 4));
        }
        {
            const int r0 = tid >> 7, c = tid & 127;
            const int r = (r0 < 2) ? r0 + 1 : r0 + 7;   // 1,2,9,10
            const int g = g0 - 4 + r;
            if ((unsigned)g < (unsigned)NX)
                *reinterpret_cast<float4*>(B + r * SROW + 4 + c * 4) =
                    __ldcg(reinterpret_cast<const float4*>(gq + (size_t)g * NZ + c * 4));
        }
        __syncthreads();

        const int t0 = b * KST;
        float* gpo = g_P[pb ^ 1];
        float* gqo = g_Q[pb ^ 1];

        // s1: p_{n+1} = f(A, B) -> C, rows [1,10]
        substep<1, 10, false>(A, B, C, Cc, clo, chi, g0, tx, ty, sx, sz, source, t0, nullptr);
        __syncthreads();
        if (my_rec) out[(size_t)tid * NSTEPS + t0] = C[rec_off];

        // s2: p_{n+2} = f(C, A) -> B, rows [2,9]
        substep<2, 9, false>(C, A, B, Cc, clo, chi, g0, tx, ty, sx, sz, source, t0 + 1, nullptr);
        __syncthreads();
        if (my_rec) out[(size_t)tid * NSTEPS + t0 + 1] = B[rec_off];

        // s3: p_{n+3} = f(B, C) -> A, rows [3,8]; own rows -> Q[pb^1]
        substep<3, 8, true>(B, C, A, Cc, clo, chi, g0, tx, ty, sx, sz, source, t0 + 2, gqo);
        __syncthreads();
        if (my_rec) out[(size_t)tid * NSTEPS + t0 + 2] = A[rec_off];

        // s4: p_{n+4} = f(A, B) -> C, rows [4,7]; own rows -> P[pb^1]
        substep<4, 7, true>(A, B, C, Cc, clo, chi, g0, tx, ty, sx, sz, source, t0 + 3, gpo);
        __syncthreads();
        if (my_rec) out[(size_t)tid * NSTEPS + t0 + 3] = C[rec_off];

        if (tid == 0) signal_done(bid);   // counter -> base+2+b

        // rotate: A' = C (newest), B' = A, C' = B
        float* tmp = A; A = C; C = B; B = tmp;
    }
}

extern "C" void kernel_launch(void* const* d_in, const int* in_sizes, int n_in,
                              void* d_out, int out_size)
{
    const float* vel    = (const float*)d_in[0];
    const float* source = (const float*)d_in[1];
    const int*   srcx   = (const int*)d_in[2];
    const int*   srcz   = (const int*)d_in[3];
    const int*   rec_x  = (const int*)d_in[4];
    const int*   rec_z  = (const int*)d_in[5];
    float* out = (float*)d_out;

    cudaFuncSetAttribute(wave_fdtd_nb_kernel,
                         cudaFuncAttributeMaxDynamicSharedMemorySize, SMEM_BYTES);
    wave_fdtd_nb_kernel<<<NCTA, NTHR, SMEM_BYTES>>>(
        vel, source, srcx, srcz, rec_x, rec_z, out);
}